// round 8
// baseline (speedup 1.0000x reference)
#include <cuda_runtime.h>
#include <cstdint>

// x: [2][4][8][8][8][96][96] f32, W: [9][4][4][3][3][3] f32, b: [9][4] f32
// out: [2][4][6][6][8][96][96] f32
#define HW_PLANE 9216
#define TSTRIDE  104                 // floats per slab row: [pad3][w-1@3][w0..95][w96@100][pad]
#define SLOTF    (4 * TSTRIDE)       // floats per slot (4 rows) = 416
typedef unsigned long long u64;

__device__ __forceinline__ void cp_async16(uint32_t saddr, const void* g, int srcsize) {
    asm volatile("cp.async.cg.shared.global [%0], [%1], 16, %2;\n"
                 :: "r"(saddr), "l"(g), "r"(srcsize));
}
__device__ __forceinline__ void cp_commit() {
    asm volatile("cp.async.commit_group;\n" ::: "memory");
}
__device__ __forceinline__ void cp_wait1() {
    asm volatile("cp.async.wait_group 1;\n" ::: "memory");
}
__device__ __forceinline__ u64 pack2(float lo, float hi) {
    u64 r; asm("mov.b64 %0, {%1, %2};" : "=l"(r) : "f"(lo), "f"(hi)); return r;
}
__device__ __forceinline__ void ffma2(u64& a, u64 x, u64 w) {
    asm("fma.rn.f32x2 %0, %1, %2, %0;" : "+l"(a) : "l"(x), "l"(w));
}
__device__ __forceinline__ float2 unpack2(u64 v) {
    float lo, hi; asm("mov.b64 {%0, %1}, %2;" : "=f"(lo), "=f"(hi) : "l"(v));
    return make_float2(lo, hi);
}

// Block: 256 threads = 8 warps. Warp = 2 output rows x 96 cols (lane: 3 cols), 4 o-chans.
// 108 iters = 36 macro-iters (ci,i,j) x kd(0,1,2) static inner. Per-warp private slabs,
// warp self-paced. FMA inner loop emitted as an operand-reuse serpentine so consecutive
// FFMA2s share a source register slot (RF-bank rt 3 -> ~2). 4 blocks/SM.
__global__ __launch_bounds__(256, 4)
void conv5d_kernel(const float* __restrict__ x,
                   const float* __restrict__ Wg,
                   const float* __restrict__ bg,
                   float* __restrict__ out)
{
    extern __shared__ __align__(16) float tiles[];     // [8 warps][3 slots][SLOTF]
    __shared__ __align__(16) float wsh[3888];          // [n(108)][tap(9)][o(4)]
    __shared__ float mbsh[4];

    const int tid   = threadIdx.x;
    const int warp  = tid >> 5;
    const int lane  = tid & 31;
    const int htile = blockIdx.x % 6;
    const int d     = blockIdx.x / 6;
    const int t     = blockIdx.y;
    const int c     = blockIdx.z % 6;
    const int b     = blockIdx.z / 6;
    const int h0    = htile * 16;

    // ---- stage weights: wsh[n*36 + tap*4 + o], n = (ci*9+ij)*3+kd
    for (int idx = tid; idx < 3888; idx += 256) {
        int o   = idx & 3;
        int tap = (idx >> 2) % 9;
        int kd  = (idx / 36) % 3;
        int ij  = (idx / 108) % 9;
        int ci  = idx / 972;
        int kh = tap / 3, kw = tap - kh * 3;
        wsh[idx] = Wg[((ij * 4 + o) * 4 + ci) * 27 + kd * 9 + kh * 3 + kw];
    }
    if (tid < 4) {
        float s = 0.f;
        #pragma unroll
        for (int ij = 0; ij < 9; ij++) s += bg[ij * 4 + tid];
        mbsh[tid] = s * (1.0f / 9.0f);
    }

    float* slab = tiles + warp * (3 * SLOTF);
    // halo columns (w=-1, w=96) are conv zero padding: zero once per slot row
    if (lane < 24) {
        int slot = lane / 8, row = (lane >> 1) & 3, side = lane & 1;
        slab[slot * SLOTF + row * TSTRIDE + (side ? 100 : 3)] = 0.f;
    }

    // ---- per-lane cp.async chunk descriptors, packed u32: [0:10) smem fidx, [10:24) gmem fidx, [24] valid
    uint32_t pk[3];
    #pragma unroll
    for (int e = 0; e < 3; e++) {
        int chunk = lane + 32 * e;
        int row = chunk / 24;
        int col = chunk - row * 24;
        int h = h0 + 2 * warp - 1 + row;       // rows 2w-1 .. 2w+2 of the block tile
        bool hv = (h >= 0 && h < 96);
        uint32_t so = (uint32_t)(row * TSTRIDE + 4 + col * 4);
        uint32_t go = (uint32_t)((hv ? h : 0) * 96 + col * 4);
        pk[e] = so | (go << 10) | (hv ? (1u << 24) : 0u);
    }
    const uint32_t sbase = (uint32_t)__cvta_generic_to_shared(slab);

    auto issue = [&](uint32_t sslot, const float* plane, bool dv) {
        #pragma unroll
        for (int e = 0; e < 3; e++) {
            uint32_t p  = pk[e];
            uint32_t so = p & 1023u;
            uint32_t go = (p >> 10) & 16383u;
            int sz = (dv && (p >> 24)) ? 16 : 0;
            cp_async16(sslot + so * 4u, plane + go, sz);
        }
    };

    // accumulators: (o0,o1) and (o2,o3) pairs, [py][px], px = 0..2
    u64 a01[2][3], a23[2][3];
    #pragma unroll
    for (int py = 0; py < 2; py++)
        #pragma unroll
        for (int px = 0; px < 3; px++) { a01[py][px] = 0ull; a23[py][px] = 0ull; }

    auto loadrow = [&](const float* rw, u64* p) {
        #pragma unroll
        for (int k = 0; k < 5; k++) { float v = rw[k]; p[k] = pack2(v, v); }
    };
    // one kh tap-row applied to two output rows; serpentine order: every instruction
    // after the first in each kw-chain shares one source operand slot with its
    // predecessor (x = pixel pair, or w = weight pair) -> RF-bank reuse.
    auto fmakh = [&](const u64* p0, const u64* p1,
                     ulonglong2 w0, ulonglong2 w1, ulonglong2 w2) {
        #pragma unroll
        for (int kw = 0; kw < 3; kw++) {
            ulonglong2 wk = (kw == 0) ? w0 : ((kw == 1) ? w1 : w2);
            ffma2(a01[0][0], p0[0 + kw], wk.x);   // start
            ffma2(a23[0][0], p0[0 + kw], wk.y);   // x-share
            ffma2(a23[1][0], p1[0 + kw], wk.y);   // w-share
            ffma2(a01[1][0], p1[0 + kw], wk.x);   // x-share
            ffma2(a01[1][1], p1[1 + kw], wk.x);   // w-share
            ffma2(a23[1][1], p1[1 + kw], wk.y);   // x-share
            ffma2(a23[0][1], p0[1 + kw], wk.y);   // w-share
            ffma2(a01[0][1], p0[1 + kw], wk.x);   // x-share
            ffma2(a01[0][2], p0[2 + kw], wk.x);   // w-share
            ffma2(a23[0][2], p0[2 + kw], wk.y);   // x-share
            ffma2(a23[1][2], p1[2 + kw], wk.y);   // w-share
            ffma2(a01[1][2], p1[2 + kw], wk.x);   // x-share
        }
    };
    auto compute = [&](int n, const float* tb) {
        const ulonglong2* wb = reinterpret_cast<const ulonglong2*>(&wsh[n * 36]);
        u64 pa[5], pb[5];
        loadrow(tb,               pa);
        loadrow(tb + TSTRIDE,     pb);
        fmakh(pa, pb, wb[0], wb[1], wb[2]);
        loadrow(tb + 2 * TSTRIDE, pa);
        fmakh(pb, pa, wb[3], wb[4], wb[5]);
        loadrow(tb + 3 * TSTRIDE, pb);
        fmakh(pa, pb, wb[6], wb[7], wb[8]);
    };

    const bool dval0 = (d >= 1), dval2 = (d <= 6);
    const float* bm = x + (size_t)b * (4 * 8 * 8 * 8 * HW_PLANE)
                    + ((size_t)((c * 8 + t) * 8) + (d - 1)) * HW_PLANE;  // macro-0 base (dz=d-1)

    // prologue: n=0 (kd'=0, slot0), n=1 (kd'=1, slot1)
    issue(sbase,             dval0 ? bm : bm + HW_PLANE, dval0); cp_commit();
    issue(sbase + SLOTF * 4, bm + HW_PLANE,              true);  cp_commit();

    __syncthreads();     // wsh/mbsh ready; no block barrier beyond this point

    const float* lanebase = slab + 3 + 3 * lane;
    int n = 0;

    #pragma unroll 1
    for (int ci = 0; ci < 4; ci++) {
        #pragma unroll 1
        for (int i = 0; i < 3; i++) {
            #pragma unroll
            for (int j = 0; j < 3; j++) {
                const bool last = (ci == 3) && (i == 2) && (j == 2);
                const float* bn = bm + (size_t)((j < 2) ? 8 : ((i < 2) ? 48 : 368)) * HW_PLANE;

                // kd = 0: compute slot0, issue (macro m, kd'=2) -> slot2
                cp_wait1(); __syncwarp();
                issue(sbase + 2 * SLOTF * 4, dval2 ? bm + 2 * HW_PLANE : bm + HW_PLANE, dval2);
                cp_commit();
                compute(n, lanebase);

                // kd = 1: compute slot1, issue (macro m+1, kd'=0) -> slot0
                cp_wait1(); __syncwarp();
                if (!last) issue(sbase, dval0 ? bn : bn + HW_PLANE, dval0);
                cp_commit();
                compute(n + 1, lanebase + SLOTF);

                // kd = 2: compute slot2, issue (macro m+1, kd'=1) -> slot1
                cp_wait1(); __syncwarp();
                if (!last) issue(sbase + SLOTF * 4, bn + HW_PLANE, true);
                cp_commit();
                compute(n + 2, lanebase + 2 * SLOTF);

                n += 3;
                bm = bn;
            }
        }
    }

    // ---- epilogue: out[b][o][c][t][d][h][w]
    const float invn = 1.0f / 9.0f;
    const float mb0 = mbsh[0], mb1 = mbsh[1], mb2 = mbsh[2], mb3 = mbsh[3];
    size_t ob = ((((size_t)(b * 4) * 6 + c) * 6 + t) * 8 + d) * (size_t)HW_PLANE;
    const size_t ostride = (size_t)6 * 6 * 8 * HW_PLANE;

    #pragma unroll
    for (int py = 0; py < 2; py++) {
        int h = h0 + 2 * warp + py;
        size_t rowoff = ob + (size_t)h * 96 + 3 * lane;
        #pragma unroll
        for (int px = 0; px < 3; px++) {
            float2 q01 = unpack2(a01[py][px]);
            float2 q23 = unpack2(a23[py][px]);
            out[rowoff + px]               = fmaf(q01.x, invn, mb0);
            out[rowoff + ostride + px]     = fmaf(q01.y, invn, mb1);
            out[rowoff + 2 * ostride + px] = fmaf(q23.x, invn, mb2);
            out[rowoff + 3 * ostride + px] = fmaf(q23.y, invn, mb3);
        }
    }
}

extern "C" void kernel_launch(void* const* d_in, const int* in_sizes, int n_in,
                              void* d_out, int out_size) {
    const float* x  = (const float*)d_in[0];
    const float* Wg = (const float*)d_in[1];
    const float* bg = (const float*)d_in[2];
    float* out = (float*)d_out;

    const int dynsmem = 8 * 3 * SLOTF * (int)sizeof(float);   // 8 warps x 3 slots = 39936 B
    cudaFuncSetAttribute(conv5d_kernel, cudaFuncAttributeMaxDynamicSharedMemorySize, dynsmem);

    dim3 grid(48, 6, 12);   // x: htile(6) + 6*d(8); y: t(6); z: b*6+c(12)
    dim3 block(256);
    conv5d_kernel<<<grid, block, dynsmem>>>(x, Wg, bg, out);
}

// round 9
// speedup vs baseline: 1.0984x; 1.0984x over previous
#include <cuda_runtime.h>
#include <cstdint>

// x: [2][4][8][8][8][96][96] f32, W: [9][4][4][3][3][3] f32, b: [9][4] f32
// out: [2][4][6][6][8][96][96] f32
#define HW_PLANE 9216
#define TSTRIDE  104                 // floats per slab row: [pad3][w-1@3][w0..95][w96@100][pad]
#define SLOTF    (4 * TSTRIDE)       // floats per slot (4 rows) = 416
typedef unsigned long long u64;

__device__ __forceinline__ void cp_async16(uint32_t saddr, const void* g, int srcsize) {
    asm volatile("cp.async.cg.shared.global [%0], [%1], 16, %2;\n"
                 :: "r"(saddr), "l"(g), "r"(srcsize));
}
__device__ __forceinline__ void cp_commit() {
    asm volatile("cp.async.commit_group;\n" ::: "memory");
}
__device__ __forceinline__ void cp_wait1() {
    asm volatile("cp.async.wait_group 1;\n" ::: "memory");
}
__device__ __forceinline__ u64 pack2(float lo, float hi) {
    u64 r; asm("mov.b64 %0, {%1, %2};" : "=l"(r) : "f"(lo), "f"(hi)); return r;
}
__device__ __forceinline__ void ffma2(u64& a, u64 x, u64 w) {
    asm("fma.rn.f32x2 %0, %1, %2, %0;" : "+l"(a) : "l"(x), "l"(w));
}
__device__ __forceinline__ float2 unpack2(u64 v) {
    float lo, hi; asm("mov.b64 {%0, %1}, %2;" : "=f"(lo), "=f"(hi) : "l"(v));
    return make_float2(lo, hi);
}

// Winograd F(3,3) along w (verified):
//   data:   T0 = 2d0 - d1 - 2d2 + d3
//           T1 = 2d1 + d2 - d3
//           T2 = -2d1 + 3d2 - d3
//           T3 = d3 - d1
//           T4 = 2d1 - d2 - 2d3 + d4
//   weight: G0 = g0/2, G1 = (g0+g1+g2)/2, G2 = (g0-g1+g2)/6,
//           G3 = (g0+2g1+4g2)/6, G4 = g2
//   accumulate M_c += G_c * T_c over all 324 tap-rows; then
//   output:  y0 = M0+M1+M2+M3; y1 = M1-M2+2M3; y2 = M1+M2+4M3+M4
//
// Block: 256 threads = 8 warps. Warp = 2 output rows x 96 cols (lane: 3 cols), 4 o-chans.
// 108 iters = 36 macro (ci,i,j) x kd(0..2) static. Per-warp slabs, warp self-paced.
__global__ __launch_bounds__(256, 3)
void conv5d_kernel(const float* __restrict__ x,
                   const float* __restrict__ Wg,
                   const float* __restrict__ bg,
                   float* __restrict__ out)
{
    extern __shared__ __align__(16) float tiles[];     // [8 warps][3 slots][SLOTF]
    __shared__ __align__(16) float wsh[6480];          // [n(108)][kh(3)][comp(5)][o(4)]
    __shared__ float mbsh[4];

    const int tid   = threadIdx.x;
    const int warp  = tid >> 5;
    const int lane  = tid & 31;
    const int htile = blockIdx.x % 6;
    const int d     = blockIdx.x / 6;
    const int t     = blockIdx.y;
    const int c     = blockIdx.z % 6;
    const int b     = blockIdx.z / 6;
    const int h0    = htile * 16;

    // ---- stage Winograd-transformed weights
    for (int u = tid; u < 1296; u += 256) {
        int o  = u & 3;
        int kh = (u >> 2) % 3;
        int nn = u / 12;             // 0..107 = (ci*9+ij)*3+kd
        int kd = nn % 3;
        int ij = (nn / 3) % 9;
        int ci = nn / 27;
        const float* wp = Wg + ((ij * 4 + o) * 4 + ci) * 27 + kd * 9 + kh * 3;
        float g0 = wp[0], g1 = wp[1], g2 = wp[2];
        float* dst = wsh + (nn * 3 + kh) * 20 + o;     // comp stride 4
        dst[0]  = 0.5f * g0;
        dst[4]  = 0.5f * (g0 + g1 + g2);
        dst[8]  = (g0 - g1 + g2) * (1.f / 6.f);
        dst[12] = (g0 + 2.f * g1 + 4.f * g2) * (1.f / 6.f);
        dst[16] = g2;
    }
    if (tid < 4) {
        float s = 0.f;
        #pragma unroll
        for (int ij = 0; ij < 9; ij++) s += bg[ij * 4 + tid];
        mbsh[tid] = s * (1.0f / 9.0f);
    }

    float* slab = tiles + warp * (3 * SLOTF);
    // halo columns (w=-1, w=96) are conv zero padding: zero once per slot row
    if (lane < 24) {
        int slot = lane / 8, row = (lane >> 1) & 3, side = lane & 1;
        slab[slot * SLOTF + row * TSTRIDE + (side ? 100 : 3)] = 0.f;
    }

    // ---- per-lane cp.async chunk descriptors, packed u32
    uint32_t pk[3];
    #pragma unroll
    for (int e = 0; e < 3; e++) {
        int chunk = lane + 32 * e;
        int row = chunk / 24;
        int col = chunk - row * 24;
        int h = h0 + 2 * warp - 1 + row;       // rows 2w-1 .. 2w+2
        bool hv = (h >= 0 && h < 96);
        uint32_t so = (uint32_t)(row * TSTRIDE + 4 + col * 4);
        uint32_t go = (uint32_t)((hv ? h : 0) * 96 + col * 4);
        pk[e] = so | (go << 10) | (hv ? (1u << 24) : 0u);
    }
    const uint32_t sbase = (uint32_t)__cvta_generic_to_shared(slab);

    auto issue = [&](uint32_t sslot, const float* plane, bool dv) {
        #pragma unroll
        for (int e = 0; e < 3; e++) {
            uint32_t p  = pk[e];
            uint32_t so = p & 1023u;
            uint32_t go = (p >> 10) & 16383u;
            int sz = (dv && (p >> 24)) ? 16 : 0;
            cp_async16(sslot + so * 4u, plane + go, sz);
        }
    };

    // Winograd-domain accumulators: [py][comp] for (o0,o1) and (o2,o3)
    u64 a01[2][5], a23[2][5];
    #pragma unroll
    for (int py = 0; py < 2; py++)
        #pragma unroll
        for (int cm = 0; cm < 5; cm++) { a01[py][cm] = 0ull; a23[py][cm] = 0ull; }

    // load 5 inputs, transform, dup-pack
    auto transform_row = [&](const float* rw, u64* T) {
        float d0 = rw[0], d1 = rw[1], d2 = rw[2], d3 = rw[3], d4 = rw[4];
        float t3 = d3 - d1;
        float t1 = fmaf(2.f, d1, d2 - d3);
        float t2 = fmaf(3.f, d2, -fmaf(2.f, d1, d3));
        float t0 = fmaf(2.f, d0 - d2, t3);
        float t4 = fmaf(-2.f, t3, d4 - d2);
        T[0] = pack2(t0, t0);
        T[1] = pack2(t1, t1);
        T[2] = pack2(t2, t2);
        T[3] = pack2(t3, t3);
        T[4] = pack2(t4, t4);
    };
    // one kh tap-row: 5 wino comps x 2 py x 2 o-pairs = 20 FFMA2
    auto fmakh5 = [&](const u64* P0, const u64* P1, const ulonglong2* wb) {
        #pragma unroll
        for (int cm = 0; cm < 5; cm++) {
            ulonglong2 w2 = wb[cm];
            ffma2(a01[0][cm], P0[cm], w2.x); ffma2(a23[0][cm], P0[cm], w2.y);
            ffma2(a01[1][cm], P1[cm], w2.x); ffma2(a23[1][cm], P1[cm], w2.y);
        }
    };
    const ulonglong2* W2 = reinterpret_cast<const ulonglong2*>(wsh);
    auto compute = [&](int n, const float* tb) {
        const ulonglong2* wb = W2 + n * 15;
        u64 TA[5], TB[5];
        transform_row(tb,               TA);
        transform_row(tb + TSTRIDE,     TB);
        fmakh5(TA, TB, wb);            // kh = 0
        transform_row(tb + 2 * TSTRIDE, TA);
        fmakh5(TB, TA, wb + 5);        // kh = 1
        transform_row(tb + 3 * TSTRIDE, TB);
        fmakh5(TA, TB, wb + 10);       // kh = 2
    };

    const bool dval0 = (d >= 1), dval2 = (d <= 6);
    const float* bm = x + (size_t)b * (4 * 8 * 8 * 8 * HW_PLANE)
                    + ((size_t)((c * 8 + t) * 8) + (d - 1)) * HW_PLANE;

    // prologue: n=0 (kd'=0, slot0), n=1 (kd'=1, slot1)
    issue(sbase,             dval0 ? bm : bm + HW_PLANE, dval0); cp_commit();
    issue(sbase + SLOTF * 4, bm + HW_PLANE,              true);  cp_commit();

    __syncthreads();     // wsh/mbsh ready; no block barrier beyond this point

    const float* lanebase = slab + 3 + 3 * lane;
    int n = 0;

    #pragma unroll 1
    for (int ci = 0; ci < 4; ci++) {
        #pragma unroll 1
        for (int i = 0; i < 3; i++) {
            #pragma unroll
            for (int j = 0; j < 3; j++) {
                const bool last = (ci == 3) && (i == 2) && (j == 2);
                const float* bn = bm + (size_t)((j < 2) ? 8 : ((i < 2) ? 48 : 368)) * HW_PLANE;

                // kd = 0: compute slot0, issue (macro m, kd'=2) -> slot2
                cp_wait1(); __syncwarp();
                issue(sbase + 2 * SLOTF * 4, dval2 ? bm + 2 * HW_PLANE : bm + HW_PLANE, dval2);
                cp_commit();
                compute(n, lanebase);

                // kd = 1: compute slot1, issue (macro m+1, kd'=0) -> slot0
                cp_wait1(); __syncwarp();
                if (!last) issue(sbase, dval0 ? bn : bn + HW_PLANE, dval0);
                cp_commit();
                compute(n + 1, lanebase + SLOTF);

                // kd = 2: compute slot2, issue (macro m+1, kd'=1) -> slot1
                cp_wait1(); __syncwarp();
                if (!last) issue(sbase + SLOTF * 4, bn + HW_PLANE, true);
                cp_commit();
                compute(n + 2, lanebase + 2 * SLOTF);

                n += 3;
                bm = bn;
            }
        }
    }

    // ---- epilogue: inverse Winograd transform + scale + bias
    const float invn = 1.0f / 9.0f;
    const float mb[4] = { mbsh[0], mbsh[1], mbsh[2], mbsh[3] };
    size_t ob = ((((size_t)(b * 4) * 6 + c) * 6 + t) * 8 + d) * (size_t)HW_PLANE;
    const size_t ostride = (size_t)6 * 6 * 8 * HW_PLANE;

    #pragma unroll
    for (int py = 0; py < 2; py++) {
        int h = h0 + 2 * warp + py;
        size_t rowoff = ob + (size_t)h * 96 + 3 * lane;
        float2 A[5], B[5];
        #pragma unroll
        for (int cm = 0; cm < 5; cm++) {
            A[cm] = unpack2(a01[py][cm]);
            B[cm] = unpack2(a23[py][cm]);
        }
        float M[4][5];
        #pragma unroll
        for (int cm = 0; cm < 5; cm++) {
            M[0][cm] = A[cm].x; M[1][cm] = A[cm].y;
            M[2][cm] = B[cm].x; M[3][cm] = B[cm].y;
        }
        #pragma unroll
        for (int o = 0; o < 4; o++) {
            float y0 = M[o][0] + M[o][1] + M[o][2] + M[o][3];
            float y1 = M[o][1] - M[o][2] + 2.f * M[o][3];
            float y2 = M[o][1] + M[o][2] + fmaf(4.f, M[o][3], M[o][4]);
            float* op = out + rowoff + (size_t)o * ostride;
            op[0] = fmaf(y0, invn, mb[o]);
            op[1] = fmaf(y1, invn, mb[o]);
            op[2] = fmaf(y2, invn, mb[o]);
        }
    }
}

extern "C" void kernel_launch(void* const* d_in, const int* in_sizes, int n_in,
                              void* d_out, int out_size) {
    const float* x  = (const float*)d_in[0];
    const float* Wg = (const float*)d_in[1];
    const float* bg = (const float*)d_in[2];
    float* out = (float*)d_out;

    const int dynsmem = 8 * 3 * SLOTF * (int)sizeof(float);   // 39936 B
    cudaFuncSetAttribute(conv5d_kernel, cudaFuncAttributeMaxDynamicSharedMemorySize, dynsmem);

    dim3 grid(48, 6, 12);   // x: htile(6) + 6*d(8); y: t(6); z: b*6+c(12)
    dim3 block(256);
    conv5d_kernel<<<grid, block, dynsmem>>>(x, Wg, bg, out);
}

// round 11
// speedup vs baseline: 1.1905x; 1.0839x over previous
#include <cuda_runtime.h>
#include <cstdint>

// x: [2][4][8][8][8][96][96] f32, W: [9][4][4][3][3][3] f32, b: [9][4] f32
// out: [2][4][6][6][8][96][96] f32
#define HW_PLANE 9216
#define SLOTF    384                 // floats per slot: 4 rows x 96, unpadded (gmem layout)
typedef unsigned long long u64;

__device__ __forceinline__ u64 pack2(float lo, float hi) {
    u64 r; asm("mov.b64 %0, {%1, %2};" : "=l"(r) : "f"(lo), "f"(hi)); return r;
}
__device__ __forceinline__ void ffma2(u64& a, u64 x, u64 w) {
    asm("fma.rn.f32x2 %0, %1, %2, %0;" : "+l"(a) : "l"(x), "l"(w));
}
__device__ __forceinline__ float2 unpack2(u64 v) {
    float lo, hi; asm("mov.b64 {%0, %1}, %2;" : "=f"(lo), "=f"(hi) : "l"(v));
    return make_float2(lo, hi);
}
__device__ __forceinline__ void mbar_init(uint32_t mbar) {
    asm volatile("mbarrier.init.shared.b64 [%0], 1;" :: "r"(mbar) : "memory");
}
__device__ __forceinline__ void mbar_expect(uint32_t mbar, uint32_t bytes) {
    asm volatile("mbarrier.arrive.expect_tx.shared.b64 _, [%0], %1;"
                 :: "r"(mbar), "r"(bytes) : "memory");
}
__device__ __forceinline__ void mbar_wait(uint32_t mbar, uint32_t parity) {
    asm volatile(
        "{\n\t.reg .pred P;\n\t"
        "WL_%=:\n\t"
        "mbarrier.try_wait.parity.acquire.cta.shared::cta.b64 P, [%0], %1, 0x989680;\n\t"
        "@!P bra WL_%=;\n\t"
        "}" :: "r"(mbar), "r"(parity) : "memory");
}
__device__ __forceinline__ void bulk_g2s(uint32_t dst, const void* src, uint32_t bytes, uint32_t mbar) {
    asm volatile("cp.async.bulk.shared::cta.global.mbarrier::complete_tx::bytes [%0], [%1], %2, [%3];"
                 :: "r"(dst), "l"(src), "r"(bytes), "r"(mbar) : "memory");
}
__device__ __forceinline__ void fence_proxy_async_cta() {
    asm volatile("fence.proxy.async.shared::cta;" ::: "memory");
}

// Winograd F(3,3) along w. Block: 256 thr = 8 warps; warp = 2 out rows x 96 cols (lane: 3),
// 4 o-chans. 108 iters = 36 macro (ci,i,j) x kd(0..2), slot = kd (static). Per-warp slots
// filled by ONE cp.async.bulk each (UBLKCP) + per-warp mbarrier; no LDGSTS, no block barrier.
__global__ __launch_bounds__(256, 3)
void conv5d_kernel(const float* __restrict__ x,
                   const float* __restrict__ Wg,
                   const float* __restrict__ bg,
                   float* __restrict__ out)
{
    extern __shared__ __align__(16) float tiles[];     // [8 warps][3 slots][SLOTF] + 4 pad
    __shared__ __align__(16) float wsh[6480];          // [n(108)][kh(3)][comp(5)][o(4)]
    __shared__ __align__(8) u64 mbars[8][3];
    __shared__ float mbsh[4];

    const int tid   = threadIdx.x;
    const int warp  = tid >> 5;
    const int lane  = tid & 31;
    const int htile = blockIdx.x % 6;
    const int d     = blockIdx.x / 6;
    const int t     = blockIdx.y;
    const int c     = blockIdx.z % 6;
    const int b     = blockIdx.z / 6;
    const int h0    = htile * 16;

    // ---- stage Winograd-transformed weights (same as R9)
    for (int u = tid; u < 1296; u += 256) {
        int o  = u & 3;
        int kh = (u >> 2) % 3;
        int nn = u / 12;
        int kd = nn % 3;
        int ij = (nn / 3) % 9;
        int ci = nn / 27;
        const float* wp = Wg + ((ij * 4 + o) * 4 + ci) * 27 + kd * 9 + kh * 3;
        float g0 = wp[0], g1 = wp[1], g2 = wp[2];
        float* dst = wsh + (nn * 3 + kh) * 20 + o;
        dst[0]  = 0.5f * g0;
        dst[4]  = 0.5f * (g0 + g1 + g2);
        dst[8]  = (g0 - g1 + g2) * (1.f / 6.f);
        dst[12] = (g0 + 2.f * g1 + 4.f * g2) * (1.f / 6.f);
        dst[16] = g2;
    }
    if (tid < 4) {
        float s = 0.f;
        #pragma unroll
        for (int ij = 0; ij < 9; ij++) s += bg[ij * 4 + tid];
        mbsh[tid] = s * (1.0f / 9.0f);
    }

    float* slab = tiles + warp * (3 * SLOTF);
    const bool v0 = (d >= 1), v2 = (d <= 6);

    // ---- per-warp bulk-copy geometry: 4 gmem-contiguous rows h0+2w-1 .. h0+2w+2
    const int hstart = h0 + 2 * warp - 1;
    const int cstart = (hstart < 0) ? 0 : hstart;
    const int cend   = (hstart + 4 > 96) ? 96 : (hstart + 4);
    const uint32_t cbytes  = (uint32_t)(cend - cstart) * 384u;   // 1152 or 1536
    const uint32_t dstoffB = (uint32_t)(cstart - hstart) * 384u; // 0 or 384
    const int      srcfo   = cstart * 96;

    // ---- static zeroing: invalid h rows (once), invalid kd slots (whole slot)
    if (hstart < 0) {            // top edge warp: row0 of every slot is h=-1 -> zero
        #pragma unroll
        for (int s = 0; s < 3; s++) {
            #pragma unroll
            for (int k = 0; k < 3; k++) slab[s * SLOTF + lane * 3 + k] = 0.f;
        }
    }
    if (cend == 96 && hstart + 4 > 96) {   // bottom edge warp: row3 is h=96 -> zero
        #pragma unroll
        for (int s = 0; s < 3; s++) {
            #pragma unroll
            for (int k = 0; k < 3; k++) slab[s * SLOTF + 288 + lane * 3 + k] = 0.f;
        }
    }
    if (!v0) {                   // d=0: kd=0 plane invalid -> slot0 stays zero
        #pragma unroll
        for (int k = 0; k < 12; k++) slab[lane + 32 * k] = 0.f;
    }
    if (!v2) {                   // d=7: kd=2 plane invalid -> slot2 stays zero
        #pragma unroll
        for (int k = 0; k < 12; k++) slab[2 * SLOTF + lane + 32 * k] = 0.f;
    }

    const uint32_t sb    = (uint32_t)__cvta_generic_to_shared(slab);
    const uint32_t mb0   = (uint32_t)__cvta_generic_to_shared(&mbars[warp][0]);
    const uint32_t mb1   = mb0 + 8, mb2 = mb0 + 16;
    if (lane == 0) { mbar_init(mb0); mbar_init(mb1); mbar_init(mb2); }
    fence_proxy_async_cta();
    __syncthreads();             // wsh/mbsh/mbar init visible; only barrier in the kernel

    // issue one slot: elect lane does expect_tx + bulk
    auto issue = [&](int s, uint32_t mb, const float* plane) {
        if (lane == 0) {
            mbar_expect(mb, cbytes);
            bulk_g2s(sb + (uint32_t)s * (SLOTF * 4) + dstoffB, plane + srcfo, cbytes, mb);
        }
    };

    // Winograd-domain accumulators
    u64 a01[2][5], a23[2][5];
    #pragma unroll
    for (int py = 0; py < 2; py++) {
        #pragma unroll
        for (int cm = 0; cm < 5; cm++) { a01[py][cm] = 0ull; a23[py][cm] = 0ull; }
    }

    const int  lzoff = (lane == 0) ? 0 : -1;   // clamped offset for w=-1 tap
    const bool lz    = (lane == 0);
    const bool rz    = (lane == 31);

    auto transform_row = [&](const float* rw, u64* T) {
        float am = rw[lzoff];
        float d0 = lz ? 0.f : am;
        float d1 = rw[0], d2 = rw[1], d3 = rw[2];
        float a4 = rw[3];
        float d4 = rz ? 0.f : a4;
        float t3 = d3 - d1;
        float t1 = fmaf(2.f, d1, d2 - d3);
        float t2 = fmaf(3.f, d2, -fmaf(2.f, d1, d3));
        float t0 = fmaf(2.f, d0 - d2, t3);
        float t4 = fmaf(-2.f, t3, d4 - d2);
        T[0] = pack2(t0, t0); T[1] = pack2(t1, t1); T[2] = pack2(t2, t2);
        T[3] = pack2(t3, t3); T[4] = pack2(t4, t4);
    };
    auto fmakh5 = [&](const u64* P0, const u64* P1, const ulonglong2* wb) {
        #pragma unroll
        for (int cm = 0; cm < 5; cm++) {
            ulonglong2 w2 = wb[cm];
            ffma2(a01[0][cm], P0[cm], w2.x); ffma2(a23[0][cm], P0[cm], w2.y);
            ffma2(a01[1][cm], P1[cm], w2.x); ffma2(a23[1][cm], P1[cm], w2.y);
        }
    };
    const ulonglong2* W2 = reinterpret_cast<const ulonglong2*>(wsh);
    auto compute = [&](int n, const float* slot) {
        const ulonglong2* wb = W2 + n * 15;
        const float* tb = slot + 3 * lane;
        u64 TA[5], TB[5];
        transform_row(tb,       TA);
        transform_row(tb + 96,  TB);
        fmakh5(TA, TB, wb);
        transform_row(tb + 192, TA);
        fmakh5(TB, TA, wb + 5);
        transform_row(tb + 288, TB);
        fmakh5(TA, TB, wb + 10);
    };

    const float* bm = x + (size_t)b * (4 * 8 * 8 * 8 * HW_PLANE)
                    + ((size_t)((c * 8 + t) * 8) + (d - 1)) * HW_PLANE;  // dz = d-1 plane

    // prologue: slot0 (kd0, macro0) if valid; slot1 (kd1, macro0)
    if (v0) issue(0, mb0, bm);
    issue(1, mb1, bm + HW_PLANE);

    uint32_t p0 = 0, p1 = 0, p2 = 0;
    int n = 0;

    #pragma unroll 1
    for (int ci = 0; ci < 4; ci++) {
        #pragma unroll 1
        for (int i = 0; i < 3; i++) {
            #pragma unroll
            for (int j = 0; j < 3; j++) {
                const bool last = (ci == 3) && (i == 2) && (j == 2);
                const float* bn = bm + (size_t)((j < 2) ? 8 : ((i < 2) ? 48 : 368)) * HW_PLANE;

                // kd = 0: wait slot0, issue (macro m, kd2) -> slot2, compute slot0
                if (v0) { mbar_wait(mb0, p0); p0 ^= 1u; }
                if (v2) issue(2, mb2, bm + 2 * HW_PLANE);
                compute(n, slab);

                // kd = 1: wait slot1, issue (macro m+1, kd0) -> slot0, compute slot1
                mbar_wait(mb1, p1); p1 ^= 1u;
                if (!last && v0) issue(0, mb0, bn);
                compute(n + 1, slab + SLOTF);

                // kd = 2: wait slot2, issue (macro m+1, kd1) -> slot1, compute slot2
                if (v2) { mbar_wait(mb2, p2); p2 ^= 1u; }
                if (!last) issue(1, mb1, bn + HW_PLANE);
                compute(n + 2, slab + 2 * SLOTF);

                n += 3;
                bm = bn;
            }
        }
    }

    // ---- epilogue: inverse Winograd + scale + bias
    const float invn = 1.0f / 9.0f;
    const float mb[4] = { mbsh[0], mbsh[1], mbsh[2], mbsh[3] };
    size_t ob = ((((size_t)(b * 4) * 6 + c) * 6 + t) * 8 + d) * (size_t)HW_PLANE;
    const size_t ostride = (size_t)6 * 6 * 8 * HW_PLANE;

    #pragma unroll
    for (int py = 0; py < 2; py++) {
        int h = h0 + 2 * warp + py;
        size_t rowoff = ob + (size_t)h * 96 + 3 * lane;
        float M[4][5];
        #pragma unroll
        for (int cm = 0; cm < 5; cm++) {
            float2 A = unpack2(a01[py][cm]);
            float2 B = unpack2(a23[py][cm]);
            M[0][cm] = A.x; M[1][cm] = A.y; M[2][cm] = B.x; M[3][cm] = B.y;
        }
        #pragma unroll
        for (int o = 0; o < 4; o++) {
            float y0 = M[o][0] + M[o][1] + M[o][2] + M[o][3];
            float y1 = M[o][1] - M[o][2] + 2.f * M[o][3];
            float y2 = M[o][1] + M[o][2] + fmaf(4.f, M[o][3], M[o][4]);
            float* op = out + rowoff + (size_t)o * ostride;
            op[0] = fmaf(y0, invn, mb[o]);
            op[1] = fmaf(y1, invn, mb[o]);
            op[2] = fmaf(y2, invn, mb[o]);
        }
    }
}

extern "C" void kernel_launch(void* const* d_in, const int* in_sizes, int n_in,
                              void* d_out, int out_size) {
    const float* x  = (const float*)d_in[0];
    const float* Wg = (const float*)d_in[1];
    const float* bg = (const float*)d_in[2];
    float* out = (float*)d_out;

    const int dynsmem = (8 * 3 * SLOTF + 4) * (int)sizeof(float);   // +4 floats overread pad
    cudaFuncSetAttribute(conv5d_kernel, cudaFuncAttributeMaxDynamicSharedMemorySize, dynsmem);

    dim3 grid(48, 6, 12);   // x: htile(6) + 6*d(8); y: t(6); z: b*6+c(12)
    dim3 block(256);
    conv5d_kernel<<<grid, block, dynsmem>>>(x, Wg, bg, out);
}

// round 12
// speedup vs baseline: 1.3583x; 1.1409x over previous
#include <cuda_runtime.h>
#include <cstdint>

// x: [2][4][8][8][8][96][96] f32, W: [9][4][4][3][3][3] f32, b: [9][4] f32
// out: [2][4][6][6][8][96][96] f32
#define HW_PLANE 9216
#define SLOTF    480                 // floats per slot: 5 rows x 96, unpadded (gmem layout)
typedef unsigned long long u64;

__device__ __forceinline__ u64 pack2(float lo, float hi) {
    u64 r; asm("mov.b64 %0, {%1, %2};" : "=l"(r) : "f"(lo), "f"(hi)); return r;
}
__device__ __forceinline__ void ffma2(u64& a, u64 x, u64 w) {
    asm("fma.rn.f32x2 %0, %1, %2, %0;" : "+l"(a) : "l"(x), "l"(w));
}
__device__ __forceinline__ float2 unpack2(u64 v) {
    float lo, hi; asm("mov.b64 {%0, %1}, %2;" : "=f"(lo), "=f"(hi) : "l"(v));
    return make_float2(lo, hi);
}
__device__ __forceinline__ void mbar_init(uint32_t mbar) {
    asm volatile("mbarrier.init.shared.b64 [%0], 1;" :: "r"(mbar) : "memory");
}
__device__ __forceinline__ void mbar_expect(uint32_t mbar, uint32_t bytes) {
    asm volatile("mbarrier.arrive.expect_tx.shared.b64 _, [%0], %1;"
                 :: "r"(mbar), "r"(bytes) : "memory");
}
__device__ __forceinline__ void mbar_wait(uint32_t mbar, uint32_t parity) {
    asm volatile(
        "{\n\t.reg .pred P;\n\t"
        "WL_%=:\n\t"
        "mbarrier.try_wait.parity.acquire.cta.shared::cta.b64 P, [%0], %1, 0x989680;\n\t"
        "@!P bra WL_%=;\n\t"
        "}" :: "r"(mbar), "r"(parity) : "memory");
}
__device__ __forceinline__ void bulk_g2s(uint32_t dst, const void* src, uint32_t bytes, uint32_t mbar) {
    asm volatile("cp.async.bulk.shared::cta.global.mbarrier::complete_tx::bytes [%0], [%1], %2, [%3];"
                 :: "r"(dst), "l"(src), "r"(bytes), "r"(mbar) : "memory");
}
__device__ __forceinline__ void fence_proxy_async_cta() {
    asm volatile("fence.proxy.async.shared::cta;" ::: "memory");
}

// Winograd F(3,3) along w. Block: 256 thr = 8 warps; warp = 3 out rows x 96 cols (lane: 3),
// 4 o-chans. 108 iters = 36 macro (ci,i,j) x kd(0..2), slot = kd. Per-warp 5-row slots via
// one cp.async.bulk + per-warp mbarrier; no LDGSTS, no block barrier in loop. 2 blocks/SM.
__global__ __launch_bounds__(256, 2)
void conv5d_kernel(const float* __restrict__ x,
                   const float* __restrict__ Wg,
                   const float* __restrict__ bg,
                   float* __restrict__ out)
{
    extern __shared__ __align__(16) float tiles[];     // [8 warps][3 slots][SLOTF] + 4 pad
    __shared__ __align__(16) float wsh[6480];          // [n(108)][kh(3)][comp(5)][o(4)]
    __shared__ __align__(8) u64 mbars[8][3];
    __shared__ float mbsh[4];

    const int tid   = threadIdx.x;
    const int warp  = tid >> 5;
    const int lane  = tid & 31;
    const int htile = blockIdx.x % 4;
    const int d     = blockIdx.x / 4;
    const int t     = blockIdx.y;
    const int c     = blockIdx.z % 6;
    const int b     = blockIdx.z / 6;
    const int h0    = htile * 24;

    // ---- stage Winograd-transformed weights
    for (int u = tid; u < 1296; u += 256) {
        int o  = u & 3;
        int kh = (u >> 2) % 3;
        int nn = u / 12;
        int kd = nn % 3;
        int ij = (nn / 3) % 9;
        int ci = nn / 27;
        const float* wp = Wg + ((ij * 4 + o) * 4 + ci) * 27 + kd * 9 + kh * 3;
        float g0 = wp[0], g1 = wp[1], g2 = wp[2];
        float* dst = wsh + (nn * 3 + kh) * 20 + o;
        dst[0]  = 0.5f * g0;
        dst[4]  = 0.5f * (g0 + g1 + g2);
        dst[8]  = (g0 - g1 + g2) * (1.f / 6.f);
        dst[12] = (g0 + 2.f * g1 + 4.f * g2) * (1.f / 6.f);
        dst[16] = g2;
    }
    if (tid < 4) {
        float s = 0.f;
        #pragma unroll
        for (int ij = 0; ij < 9; ij++) s += bg[ij * 4 + tid];
        mbsh[tid] = s * (1.0f / 9.0f);
    }

    float* slab = tiles + warp * (3 * SLOTF);
    const bool v0 = (d >= 1), v2 = (d <= 6);

    // ---- per-warp bulk-copy geometry: 5 gmem-contiguous rows h0+3w-1 .. h0+3w+3
    const int hstart = h0 + 3 * warp - 1;
    const int cstart = (hstart < 0) ? 0 : hstart;
    const int cend   = (hstart + 5 > 96) ? 96 : (hstart + 5);
    const uint32_t cbytes  = (uint32_t)(cend - cstart) * 384u;   // 1920 or 1536
    const uint32_t dstoffB = (uint32_t)(cstart - hstart) * 384u; // 0 or 384
    const int      srcfo   = cstart * 96;

    // ---- static zeroing: invalid h rows, invalid kd slots
    if (hstart < 0) {            // h=-1 row (row0) of every slot
        #pragma unroll
        for (int s = 0; s < 3; s++) {
            #pragma unroll
            for (int k = 0; k < 3; k++) slab[s * SLOTF + lane * 3 + k] = 0.f;
        }
    }
    if (hstart + 5 > 96) {       // h=96 row (row4) of every slot
        #pragma unroll
        for (int s = 0; s < 3; s++) {
            #pragma unroll
            for (int k = 0; k < 3; k++) slab[s * SLOTF + 384 + lane * 3 + k] = 0.f;
        }
    }
    if (!v0) {                   // d=0: slot0 stays zero
        #pragma unroll
        for (int k = 0; k < 15; k++) slab[lane + 32 * k] = 0.f;
    }
    if (!v2) {                   // d=7: slot2 stays zero
        #pragma unroll
        for (int k = 0; k < 15; k++) slab[2 * SLOTF + lane + 32 * k] = 0.f;
    }

    const uint32_t sb  = (uint32_t)__cvta_generic_to_shared(slab);
    const uint32_t mb0 = (uint32_t)__cvta_generic_to_shared(&mbars[warp][0]);
    const uint32_t mb1 = mb0 + 8, mb2 = mb0 + 16;
    if (lane == 0) { mbar_init(mb0); mbar_init(mb1); mbar_init(mb2); }
    fence_proxy_async_cta();
    __syncthreads();             // wsh/mbsh/mbar init visible; only block barrier

    auto issue = [&](int s, uint32_t mb, const float* plane) {
        if (lane == 0) {
            mbar_expect(mb, cbytes);
            bulk_g2s(sb + (uint32_t)s * (SLOTF * 4) + dstoffB, plane + srcfo, cbytes, mb);
        }
    };

    // Winograd-domain accumulators: 3 output rows x 5 comps x 2 o-pairs
    u64 a01[3][5], a23[3][5];
    #pragma unroll
    for (int py = 0; py < 3; py++) {
        #pragma unroll
        for (int cm = 0; cm < 5; cm++) { a01[py][cm] = 0ull; a23[py][cm] = 0ull; }
    }

    const int  lzoff = (lane == 0) ? 0 : -1;
    const bool lz    = (lane == 0);
    const bool rz    = (lane == 31);

    auto transform_row = [&](const float* rw, u64* T) {
        float am = rw[lzoff];
        float d0 = lz ? 0.f : am;
        float d1 = rw[0], d2 = rw[1], d3 = rw[2];
        float a4 = rw[3];
        float d4 = rz ? 0.f : a4;
        float t3 = d3 - d1;
        float t1 = fmaf(2.f, d1, d2 - d3);
        float t2 = fmaf(3.f, d2, -fmaf(2.f, d1, d3));
        float t0 = fmaf(2.f, d0 - d2, t3);
        float t4 = fmaf(-2.f, t3, d4 - d2);
        T[0] = pack2(t0, t0); T[1] = pack2(t1, t1); T[2] = pack2(t2, t2);
        T[3] = pack2(t3, t3); T[4] = pack2(t4, t4);
    };
    // one kh tap-row to 3 output rows: py0<-P0, py1<-P1, py2<-P2  (30 FFMA2)
    auto fmakh3 = [&](const u64* P0, const u64* P1, const u64* P2, const ulonglong2* wb) {
        #pragma unroll
        for (int cm = 0; cm < 5; cm++) {
            ulonglong2 w2 = wb[cm];
            ffma2(a01[0][cm], P0[cm], w2.x); ffma2(a23[0][cm], P0[cm], w2.y);
            ffma2(a01[1][cm], P1[cm], w2.x); ffma2(a23[1][cm], P1[cm], w2.y);
            ffma2(a01[2][cm], P2[cm], w2.x); ffma2(a23[2][cm], P2[cm], w2.y);
        }
    };
    const ulonglong2* W2 = reinterpret_cast<const ulonglong2*>(wsh);
    auto compute = [&](int n, const float* slot) {
        const ulonglong2* wb = W2 + n * 15;
        const float* tb = slot + 3 * lane;
        u64 R0[5], R1[5], R2[5];
        transform_row(tb,        R0);
        transform_row(tb + 96,   R1);
        transform_row(tb + 192,  R2);
        fmakh3(R0, R1, R2, wb);          // kh = 0 (rows 0,1,2)
        transform_row(tb + 288,  R0);    // row 3
        fmakh3(R1, R2, R0, wb + 5);      // kh = 1 (rows 1,2,3)
        transform_row(tb + 384,  R1);    // row 4
        fmakh3(R2, R0, R1, wb + 10);     // kh = 2 (rows 2,3,4)
    };

    const float* bm = x + (size_t)b * (4 * 8 * 8 * 8 * HW_PLANE)
                    + ((size_t)((c * 8 + t) * 8) + (d - 1)) * HW_PLANE;  // dz = d-1 plane

    if (v0) issue(0, mb0, bm);
    issue(1, mb1, bm + HW_PLANE);

    uint32_t p0 = 0, p1 = 0, p2 = 0;
    int n = 0;

    #pragma unroll 1
    for (int ci = 0; ci < 4; ci++) {
        #pragma unroll 1
        for (int i = 0; i < 3; i++) {
            #pragma unroll
            for (int j = 0; j < 3; j++) {
                const bool last = (ci == 3) && (i == 2) && (j == 2);
                const float* bn = bm + (size_t)((j < 2) ? 8 : ((i < 2) ? 48 : 368)) * HW_PLANE;

                // kd = 0
                if (v0) { mbar_wait(mb0, p0); p0 ^= 1u; }
                if (v2) issue(2, mb2, bm + 2 * HW_PLANE);
                compute(n, slab);

                // kd = 1
                mbar_wait(mb1, p1); p1 ^= 1u;
                if (!last && v0) issue(0, mb0, bn);
                compute(n + 1, slab + SLOTF);

                // kd = 2
                if (v2) { mbar_wait(mb2, p2); p2 ^= 1u; }
                if (!last) issue(1, mb1, bn + HW_PLANE);
                compute(n + 2, slab + 2 * SLOTF);

                n += 3;
                bm = bn;
            }
        }
    }

    // ---- epilogue: inverse Winograd + scale + bias
    const float invn = 1.0f / 9.0f;
    const float mb[4] = { mbsh[0], mbsh[1], mbsh[2], mbsh[3] };
    size_t ob = ((((size_t)(b * 4) * 6 + c) * 6 + t) * 8 + d) * (size_t)HW_PLANE;
    const size_t ostride = (size_t)6 * 6 * 8 * HW_PLANE;

    #pragma unroll
    for (int py = 0; py < 3; py++) {
        int h = h0 + 3 * warp + py;
        size_t rowoff = ob + (size_t)h * 96 + 3 * lane;
        float M[4][5];
        #pragma unroll
        for (int cm = 0; cm < 5; cm++) {
            float2 A = unpack2(a01[py][cm]);
            float2 B = unpack2(a23[py][cm]);
            M[0][cm] = A.x; M[1][cm] = A.y; M[2][cm] = B.x; M[3][cm] = B.y;
        }
        #pragma unroll
        for (int o = 0; o < 4; o++) {
            float y0 = M[o][0] + M[o][1] + M[o][2] + M[o][3];
            float y1 = M[o][1] - M[o][2] + 2.f * M[o][3];
            float y2 = M[o][1] + M[o][2] + fmaf(4.f, M[o][3], M[o][4]);
            float* op = out + rowoff + (size_t)o * ostride;
            op[0] = fmaf(y0, invn, mb[o]);
            op[1] = fmaf(y1, invn, mb[o]);
            op[2] = fmaf(y2, invn, mb[o]);
        }
    }
}

extern "C" void kernel_launch(void* const* d_in, const int* in_sizes, int n_in,
                              void* d_out, int out_size) {
    const float* x  = (const float*)d_in[0];
    const float* Wg = (const float*)d_in[1];
    const float* bg = (const float*)d_in[2];
    float* out = (float*)d_out;

    const int dynsmem = (8 * 3 * SLOTF + 4) * (int)sizeof(float);   // +4 floats overread pad
    cudaFuncSetAttribute(conv5d_kernel, cudaFuncAttributeMaxDynamicSharedMemorySize, dynsmem);

    dim3 grid(32, 6, 12);   // x: htile(4) + 4*d(8); y: t(6); z: b*6+c(12)
    dim3 block(256);
    conv5d_kernel<<<grid, block, dynsmem>>>(x, Wg, bg, out);
}